// round 1
// baseline (speedup 1.0000x reference)
#include <cuda_runtime.h>

// Problem constants (fixed by setup_inputs)
#define S_LEN 4096
#define BATCH 8
#define DIM 1024
#define D4 (DIM / 4)          // 256 float4 per row
#define SPLIT 49
#define SCALE 32.0f           // sqrt(1024)

// Grid: S_LEN blocks for the elementwise part + 1 block for the doc scan.
// Block = 256 threads.
//
// Elementwise blocks (blockIdx.x < S_LEN):
//   t = blockIdx.x, thread handles float4 column d = threadIdx.x.
//   Load pe[t, d] once, loop b = 0..7 reading emb and writing out.
//   out[t,b,d] = emb[t,b,d] * 32 + pe[t,d]
//
// Doc block (blockIdx.x == S_LEN):
//   8 warps, warp w owns batch column w. Pass 1 builds a 4096-bit flag
//   bitmask (128 u32 words per column) in shared memory via ballot.
//   Pass 2 does an inclusive popc-scan with a running carry:
//     cum[t]   = #splits at positions <= t
//     doc[t]   = (flag[t+1] ? 0 : cum[t])   (flag[S]=0)
__global__ __launch_bounds__(256, 8)
void pe_fused_kernel(const float4* __restrict__ emb,
                     const int*    __restrict__ src,
                     const float4* __restrict__ pe,
                     float4*       __restrict__ out,
                     float*        __restrict__ doc)
{
    const int blk = blockIdx.x;

    if (blk < S_LEN) {
        const int t = blk;
        const int d = threadIdx.x;           // 0..255
        float4 p = pe[t * D4 + d];

        #pragma unroll
        for (int b = 0; b < BATCH; b++) {
            const int idx = (t * BATCH + b) * D4 + d;
            float4 e = emb[idx];
            float4 o;
            o.x = fmaf(e.x, SCALE, p.x);
            o.y = fmaf(e.y, SCALE, p.y);
            o.z = fmaf(e.z, SCALE, p.z);
            o.w = fmaf(e.w, SCALE, p.w);
            out[idx] = o;
        }
        return;
    }

    // ---- doc scan block ----
    __shared__ unsigned words[BATCH * 128];  // 4096 bits per column

    const int warp = threadIdx.x >> 5;       // batch column 0..7
    const int lane = threadIdx.x & 31;

    // Pass 1: build flag bitmasks
    #pragma unroll 4
    for (int c = 0; c < 128; c++) {
        const int t = c * 32 + lane;
        const int v = __ldg(&src[t * BATCH + warp]);
        unsigned m = __ballot_sync(0xFFFFFFFFu, v == SPLIT);
        if (lane == 0) words[warp * 128 + c] = m;
    }
    __syncwarp();

    // Pass 2: inclusive scan + m_next zeroing
    int carry = 0;
    const unsigned le_mask = 0xFFFFFFFFu >> (31 - lane);
    for (int c = 0; c < 128; c++) {
        const unsigned m = words[warp * 128 + c];
        const int t = c * 32 + lane;
        const int incl = carry + __popc(m & le_mask);

        unsigned next_bit;
        if (lane < 31)
            next_bit = (m >> (lane + 1)) & 1u;
        else
            next_bit = (c < 127) ? (words[warp * 128 + c + 1] & 1u) : 0u;

        doc[t * BATCH + warp] = next_bit ? 0.0f : (float)incl;
        carry += __popc(m);
    }
}

extern "C" void kernel_launch(void* const* d_in, const int* in_sizes, int n_in,
                              void* d_out, int out_size)
{
    const float* emb = (const float*)d_in[0];   // [S, B, DIM] f32
    const int*   src = (const int*)  d_in[1];   // [S, B, 1]   i32
    const float* pe  = (const float*)d_in[2];   // [5000, 1, DIM] f32

    float* out = (float*)d_out;                  // first in_sizes[0] floats
    float* doc = out + (size_t)in_sizes[0];      // then S*B floats

    pe_fused_kernel<<<S_LEN + 1, 256>>>(
        (const float4*)emb, src, (const float4*)pe,
        (float4*)out, doc);
}